// round 16
// baseline (speedup 1.0000x reference)
#include <cuda_runtime.h>
#include <cuda_bf16.h>
#include <cstdint>

// Problem constants
constexpr int T_ = 1024;
constexpr int B_ = 32;
constexpr int D_ = 1024;
constexpr int M_ = T_ * B_;        // 32768 rows for the precompute GEMMs

// Scratch: fp32 results xRx ([0]) and xWd ([1]); bf16 hi/lo splits of x and W.
__device__ float g_scratch[2][(size_t)M_ * D_];
__device__ __nv_bfloat16 g_xh[(size_t)M_ * D_];
__device__ __nv_bfloat16 g_xl[(size_t)M_ * D_];
__device__ __nv_bfloat16 g_whA[D_ * D_];   // R_x hi
__device__ __nv_bfloat16 g_wlA[D_ * D_];   // R_x lo
__device__ __nv_bfloat16 g_whB[D_ * D_];   // W_delta hi
__device__ __nv_bfloat16 g_wlB[D_ * D_];   // W_delta lo

// ---------------------------------------------------------------------------
// Packed f32x2 helpers (sm_103a): one instruction = two fp32 FMAs/ADDs.
// ---------------------------------------------------------------------------
__device__ __forceinline__ void fma2(unsigned long long& d,
                                     unsigned long long a,
                                     unsigned long long b) {
    asm("fma.rn.f32x2 %0, %1, %2, %0;" : "+l"(d) : "l"(a), "l"(b));
}
__device__ __forceinline__ void add2(unsigned long long& d,
                                     unsigned long long a) {
    asm("add.rn.f32x2 %0, %0, %1;" : "+l"(d) : "l"(a));
}
__device__ __forceinline__ unsigned long long dup2(float x) {
    unsigned long long r;
    asm("mov.b64 %0, {%1, %1};" : "=l"(r) : "f"(x));
    return r;
}
__device__ __forceinline__ float2 unpk(unsigned long long v) {
    float2 r;
    asm("mov.b64 {%0, %1}, %2;" : "=f"(r.x), "=f"(r.y) : "l"(v));
    return r;
}

// ---------------------------------------------------------------------------
// Tensor-core helpers: ldmatrix + bf16 mma (fp32 accumulate).
// ---------------------------------------------------------------------------
__device__ __forceinline__ void ldsm4(uint32_t& r0, uint32_t& r1,
                                      uint32_t& r2, uint32_t& r3,
                                      uint32_t addr) {
    asm volatile("ldmatrix.sync.aligned.m8n8.x4.shared.b16 {%0,%1,%2,%3}, [%4];"
                 : "=r"(r0), "=r"(r1), "=r"(r2), "=r"(r3) : "r"(addr));
}
__device__ __forceinline__ void mma16816(float* d, const uint32_t* a,
                                         uint32_t b0, uint32_t b1) {
    asm volatile(
        "mma.sync.aligned.m16n8k16.row.col.f32.bf16.bf16.f32 "
        "{%0,%1,%2,%3}, {%4,%5,%6,%7}, {%8,%9}, {%0,%1,%2,%3};"
        : "+f"(d[0]), "+f"(d[1]), "+f"(d[2]), "+f"(d[3])
        : "r"(a[0]), "r"(a[1]), "r"(a[2]), "r"(a[3]), "r"(b0), "r"(b1));
}

// ---------------------------------------------------------------------------
// Grid barrier primitives: release-reduction arrive + acquire poll.
// ---------------------------------------------------------------------------
__device__ unsigned g_ctr;   // reset to 0 by copy_h0_kernel each launch

__device__ __forceinline__ void arrive_release(unsigned* p) {
    asm volatile("red.release.gpu.global.add.u32 [%0], 1;"
                 :: "l"(p) : "memory");
}
__device__ __forceinline__ unsigned ld_acquire(const unsigned* p) {
    unsigned v;
    asm volatile("ld.acquire.gpu.global.u32 %0, [%1];" : "=r"(v) : "l"(p)
                 : "memory");
    return v;
}

// ---------------------------------------------------------------------------
// Split kernels: v -> (bf16 hi, bf16 lo) with lo = bf16(v - float(hi)).
// ---------------------------------------------------------------------------
__global__ void __launch_bounds__(256) split_x_kernel(const float* __restrict__ x)
{
    const int n4 = M_ * D_ / 4;
    for (int i = blockIdx.x * blockDim.x + threadIdx.x; i < n4;
         i += gridDim.x * blockDim.x) {
        float4 v = ((const float4*)x)[i];
        __nv_bfloat16 h0 = __float2bfloat16(v.x);
        __nv_bfloat16 h1 = __float2bfloat16(v.y);
        __nv_bfloat16 h2 = __float2bfloat16(v.z);
        __nv_bfloat16 h3 = __float2bfloat16(v.w);
        __nv_bfloat16 l0 = __float2bfloat16(v.x - __bfloat162float(h0));
        __nv_bfloat16 l1 = __float2bfloat16(v.y - __bfloat162float(h1));
        __nv_bfloat16 l2 = __float2bfloat16(v.z - __bfloat162float(h2));
        __nv_bfloat16 l3 = __float2bfloat16(v.w - __bfloat162float(h3));
        ((__nv_bfloat162*)g_xh)[2 * i + 0] = __nv_bfloat162(h0, h1);
        ((__nv_bfloat162*)g_xh)[2 * i + 1] = __nv_bfloat162(h2, h3);
        ((__nv_bfloat162*)g_xl)[2 * i + 0] = __nv_bfloat162(l0, l1);
        ((__nv_bfloat162*)g_xl)[2 * i + 1] = __nv_bfloat162(l2, l3);
    }
}

__global__ void __launch_bounds__(256) split_w_kernel(
    const float* __restrict__ Rx, const float* __restrict__ Wd)
{
    const float* src = blockIdx.y ? Wd : Rx;
    __nv_bfloat16* dh = blockIdx.y ? g_whB : g_whA;
    __nv_bfloat16* dl = blockIdx.y ? g_wlB : g_wlA;
    const int n = D_ * D_;
    for (int i = blockIdx.x * blockDim.x + threadIdx.x; i < n;
         i += gridDim.x * blockDim.x) {
        float v = src[i];
        __nv_bfloat16 h = __float2bfloat16(v);
        dh[i] = h;
        dl[i] = __float2bfloat16(v - __bfloat162float(h));
    }
}

// ---------------------------------------------------------------------------
// Tensor-core precompute GEMM: C[m][n] = sum_k A[m][k]*W[n][k] + bias[n],
// computed as xh*wh + xh*wl + xl*wh in bf16 HMMA with fp32 accumulators.
// BM=128, BN=64, BK=32; 256 threads (8 warps as 4m x 2n); double-buffered
// dynamic SMEM, stride-40 bf16 rows (80B -> conflict-free ldmatrix).
// blockIdx.z selects (W split, bias, C) pair.
// ---------------------------------------------------------------------------
constexpr int GBM = 128, GBN = 64, GBK = 32;
constexpr int GSTR = 40;                       // bf16 elems per smem row
constexpr int AH_OFF = 0;                      // [2][128*40]
constexpr int AL_OFF = 2 * GBM * GSTR;         // 10240
constexpr int BH_OFF = AL_OFF + 2 * GBM * GSTR;    // 20480, [2][64*40]
constexpr int BL_OFF = BH_OFF + 2 * GBN * GSTR;    // 25600
constexpr int GEMM_SMEM_ELEMS = BL_OFF + 2 * GBN * GSTR;   // 30720
constexpr int GEMM_SMEM_BYTES = GEMM_SMEM_ELEMS * 2;       // 61440 B

__global__ void __launch_bounds__(256) gemm_tc_kernel(
    const float* __restrict__ b0, const float* __restrict__ b1)
{
    extern __shared__ __nv_bfloat16 smb[];
    const __nv_bfloat16* __restrict__ Wh = blockIdx.z ? g_whB : g_whA;
    const __nv_bfloat16* __restrict__ Wl = blockIdx.z ? g_wlB : g_wlA;
    const float* __restrict__ bias = blockIdx.z ? b1 : b0;
    float* __restrict__ C = g_scratch[blockIdx.z];

    const int m0 = blockIdx.y * GBM;
    const int n0 = blockIdx.x * GBN;
    const int tid = threadIdx.x;
    const int wid = tid >> 5;
    const int lane = tid & 31;
    const int wm = (wid & 3) * 32;     // warp m-offset in tile
    const int wn = (wid >> 2) * 32;    // warp n-offset in tile

    // loader mapping
    const int arow = tid >> 1;                     // 0..127 (2 chunks each)
    const int brow = tid >> 2;                     // 0..63
    const int bc   = tid & 3;                      // 16B chunk

    const __nv_bfloat16* xh_p = g_xh + (size_t)(m0 + arow) * D_;
    const __nv_bfloat16* xl_p = g_xl + (size_t)(m0 + arow) * D_;
    const __nv_bfloat16* wh_p = Wh + (size_t)(n0 + brow) * D_;
    const __nv_bfloat16* wl_p = Wl + (size_t)(n0 + brow) * D_;

    // smem bases (u32 shared addresses for ldmatrix)
    uint32_t smb_u = (uint32_t)__cvta_generic_to_shared(smb);

    // frag row/k mapping for ldmatrix x4 (canonical)
    const int lrow = lane & 15;
    const int lk8  = (lane >> 4) * 8;

    float acc[2][4][4];
#pragma unroll
    for (int i = 0; i < 2; i++)
#pragma unroll
        for (int g = 0; g < 4; g++)
#pragma unroll
            for (int r = 0; r < 4; r++) acc[i][g][r] = 0.f;

    auto sts_tile = [&](int buf, uint4 ah0, uint4 ah1, uint4 al0, uint4 al1,
                        uint4 bh, uint4 bl) {
        // A: idx = tid*2 + i; row = idx>>2, c = idx&3
        int i0 = tid * 2, i1 = tid * 2 + 1;
        int r0 = i0 >> 2, c0 = i0 & 3;
        int r1 = i1 >> 2, c1 = i1 & 3;
        *(uint4*)&smb[AH_OFF + buf * GBM * GSTR + r0 * GSTR + c0 * 8] = ah0;
        *(uint4*)&smb[AH_OFF + buf * GBM * GSTR + r1 * GSTR + c1 * 8] = ah1;
        *(uint4*)&smb[AL_OFF + buf * GBM * GSTR + r0 * GSTR + c0 * 8] = al0;
        *(uint4*)&smb[AL_OFF + buf * GBM * GSTR + r1 * GSTR + c1 * 8] = al1;
        *(uint4*)&smb[BH_OFF + buf * GBN * GSTR + brow * GSTR + bc * 8] = bh;
        *(uint4*)&smb[BL_OFF + buf * GBN * GSTR + brow * GSTR + bc * 8] = bl;
    };

    auto ldg_tile = [&](int kt, uint4& ah0, uint4& ah1, uint4& al0, uint4& al1,
                        uint4& bh, uint4& bl) {
        int i0 = tid * 2, i1 = tid * 2 + 1;
        int c0 = i0 & 3, c1 = i1 & 3;
        // note: arow == i0>>2 == i1>>2 since i1 = i0+1 and i0 even... (i0&3,i1&3 differ)
        ah0 = *(const uint4*)(xh_p + kt * GBK + c0 * 8);
        ah1 = *(const uint4*)(xh_p + kt * GBK + c1 * 8);
        al0 = *(const uint4*)(xl_p + kt * GBK + c0 * 8);
        al1 = *(const uint4*)(xl_p + kt * GBK + c1 * 8);
        bh  = *(const uint4*)(wh_p + kt * GBK + bc * 8);
        bl  = *(const uint4*)(wl_p + kt * GBK + bc * 8);
    };

    {   // prologue: tile 0 -> buffer 0
        uint4 ah0, ah1, al0, al1, bh, bl;
        ldg_tile(0, ah0, ah1, al0, al1, bh, bl);
        sts_tile(0, ah0, ah1, al0, al1, bh, bl);
    }
    __syncthreads();

    constexpr int NKT = D_ / GBK;   // 32
    int buf = 0;
    for (int kt = 1; kt <= NKT; kt++) {
        uint4 ah0, ah1, al0, al1, bh, bl;
        if (kt < NKT) ldg_tile(kt, ah0, ah1, al0, al1, bh, bl);

        // compute tile (buf)
#pragma unroll
        for (int ks = 0; ks < 2; ks++) {
            const uint32_t aoff0 =
                ((wm + 0 * 16 + lrow) * GSTR + ks * 16 + lk8) * 2;
            const uint32_t aoff1 =
                ((wm + 1 * 16 + lrow) * GSTR + ks * 16 + lk8) * 2;
            const uint32_t boff0 =
                ((wn + 0 * 16 + lrow) * GSTR + ks * 16 + lk8) * 2;
            const uint32_t boff1 =
                ((wn + 1 * 16 + lrow) * GSTR + ks * 16 + lk8) * 2;

            uint32_t aF[2][4], bH[2][4], bL[2][4];
            uint32_t aHbase = smb_u + (AH_OFF + buf * GBM * GSTR) * 2;
            uint32_t aLbase = smb_u + (AL_OFF + buf * GBM * GSTR) * 2;
            uint32_t bHbase = smb_u + (BH_OFF + buf * GBN * GSTR) * 2;
            uint32_t bLbase = smb_u + (BL_OFF + buf * GBN * GSTR) * 2;

            // A-hi frags
            ldsm4(aF[0][0], aF[0][1], aF[0][2], aF[0][3], aHbase + aoff0);
            ldsm4(aF[1][0], aF[1][1], aF[1][2], aF[1][3], aHbase + aoff1);
            // B-hi / B-lo frags (n16 groups)
            ldsm4(bH[0][0], bH[0][1], bH[0][2], bH[0][3], bHbase + boff0);
            ldsm4(bH[1][0], bH[1][1], bH[1][2], bH[1][3], bHbase + boff1);
            ldsm4(bL[0][0], bL[0][1], bL[0][2], bL[0][3], bLbase + boff0);
            ldsm4(bL[1][0], bL[1][1], bL[1][2], bL[1][3], bLbase + boff1);

            // xh*wh and xh*wl
#pragma unroll
            for (int mi = 0; mi < 2; mi++)
#pragma unroll
                for (int ng = 0; ng < 2; ng++) {
                    mma16816(acc[mi][ng * 2 + 0], aF[mi], bH[ng][0], bH[ng][2]);
                    mma16816(acc[mi][ng * 2 + 1], aF[mi], bH[ng][1], bH[ng][3]);
                    mma16816(acc[mi][ng * 2 + 0], aF[mi], bL[ng][0], bL[ng][2]);
                    mma16816(acc[mi][ng * 2 + 1], aF[mi], bL[ng][1], bL[ng][3]);
                }

            // A-lo frags (reuse regs), xl*wh
            ldsm4(aF[0][0], aF[0][1], aF[0][2], aF[0][3], aLbase + aoff0);
            ldsm4(aF[1][0], aF[1][1], aF[1][2], aF[1][3], aLbase + aoff1);
#pragma unroll
            for (int mi = 0; mi < 2; mi++)
#pragma unroll
                for (int ng = 0; ng < 2; ng++) {
                    mma16816(acc[mi][ng * 2 + 0], aF[mi], bH[ng][0], bH[ng][2]);
                    mma16816(acc[mi][ng * 2 + 1], aF[mi], bH[ng][1], bH[ng][3]);
                }
        }

        if (kt < NKT) {
            sts_tile(buf ^ 1, ah0, ah1, al0, al1, bh, bl);
        }
        __syncthreads();
        buf ^= 1;
    }

    // epilogue: bias + store fp32
#pragma unroll
    for (int mi = 0; mi < 2; mi++) {
        int row = m0 + wm + mi * 16 + (lane >> 2);
#pragma unroll
        for (int g = 0; g < 4; g++) {
            int col = n0 + wn + (g >> 1) * 16 + (g & 1) * 8 + (lane & 3) * 2;
            float bx = bias[col], by = bias[col + 1];
            *(float2*)&C[(size_t)row * D_ + col] =
                make_float2(acc[mi][g][0] + bx, acc[mi][g][1] + by);
            *(float2*)&C[(size_t)(row + 8) * D_ + col] =
                make_float2(acc[mi][g][2] + bx, acc[mi][g][3] + by);
        }
    }
}

// ---------------------------------------------------------------------------
// h0 -> H[0]; also resets the scan's grid-barrier counter for this launch
// (required for deterministic graph replays).
// ---------------------------------------------------------------------------
__global__ void copy_h0_kernel(const float* __restrict__ h0, float* __restrict__ H)
{
    int i = blockIdx.x * blockDim.x + threadIdx.x;
    if (i < B_ * D_) H[i] = h0[i];
    if (i == 0) g_ctr = 0u;
}

// ---------------------------------------------------------------------------
// Persistent recurrent scan (round-9 core — measured best).
// 128 CTAs x 512 threads. CTA owns 8 columns; weights cached once as
// interleaved (R_h,R_delta) float2 so one fma.rn.f32x2 drives both dots.
// Each of 16 warps owns a 64-wide K-slice: stages it (coalesced, warp-
// private, syncwarp only), computes all 8 columns with broadcast weight LDS,
// publishes packed partials. 256 epilogue threads fold 16 packed partials
// (2 chains), apply gates, write out & H[t+1].
// Grid barrier: release-reduction counter + acquire polling (1 L2 hop).
// ---------------------------------------------------------------------------
constexpr int NCTA = 128;
constexpr int JC = 8;                        // columns per CTA
constexpr int SB_ = 512;                     // threads per CTA
constexpr int H4S = 257;                     // float4 stride per batch row
constexpr int WVD_F = JC * D_ * 2;           // 16384 floats (interleaved pairs)
constexpr int HS_F = B_ * H4S * 4;           // 32896 floats
constexpr int RED_ROW = 33;                  // u64 per row (padded)
constexpr int RED_F = 16 * JC * RED_ROW * 2; // 8448 floats
constexpr int SMEM_FLOATS = WVD_F + HS_F + RED_F;
constexpr int SMEM_BYTES = SMEM_FLOATS * 4;  // 230912 B

__global__ void __launch_bounds__(SB_, 1) scan_kernel(
    const float* __restrict__ x,
    const float* __restrict__ Rh,
    const float* __restrict__ Rd,
    const float* __restrict__ bgate,
    float* __restrict__ out,
    float* __restrict__ H)
{
    extern __shared__ float sm[];
    float2* wvd2 = (float2*)sm;                       // [JC][D_] (Rh,Rd) pairs
    const ulonglong2* wvd_u2 = (const ulonglong2*)sm; // same, 2 k's per load
    float*  hsf = sm + WVD_F;                         // h as [B][H4S*4] floats
    float4* hs4 = (float4*)hsf;
    unsigned long long* red2 = (unsigned long long*)(sm + WVD_F + HS_F);

    const float* __restrict__ xr = g_scratch[0];
    const float* __restrict__ xw = g_scratch[1];

    const int cta = blockIdx.x;
    const int tid = threadIdx.x;
    const int j0 = cta * JC;

    // Cache this CTA's weights once, interleaved (Rh, Rd).
    for (int i = tid; i < JC * D_; i += SB_) {
        int j = i >> 10, k = i & 1023;
        wvd2[i] = make_float2(Rh[(size_t)(j0 + j) * D_ + k],
                              Rd[(size_t)(j0 + j) * D_ + k]);
    }
    __syncthreads();

    const int warp  = tid >> 5;      // 0..15, owns K-slice [warp*64, warp*64+64)
    const int b     = tid & 31;      // lane -> batch
    const int qbase = warp * 16;     // float4 index base of this warp's K-slice

    // epilogue mapping (tid < 256): column ej, batch eb
    const int ej = tid & 7;
    const int eb = tid >> 3;
    const int jg = j0 + ej;
    float bg = 0.f;
    if (tid < 256) bg = bgate[jg];

    for (int t = 0; t < T_; t++) {
        const size_t tb = (size_t)t * B_ * D_;

        // ---- prefetch epilogue inputs early (latency hidden by compute) ----
        float pre_xr = 0.f, pre_xw = 0.f, pre_x = 0.f;
        const size_t eidx = tb + (size_t)eb * D_ + jg;
        if (tid < 256) {
            pre_xr = __ldg(xr + eidx);
            pre_xw = __ldg(xw + eidx);
            pre_x  = __ldg(x + eidx);
        }

        // ---- per-warp h staging: this warp's K-slice, all batches ----
        const float4* hp = (const float4*)(H + tb);
#pragma unroll
        for (int it = 0; it < 16; it++) {
            int idx = it * 32 + b;          // coalesced
            int b2  = idx >> 4;
            int qq  = idx & 15;
            float4 v = __ldcg(hp + b2 * 256 + qbase + qq);
            hs4[b2 * H4S + qbase + qq] = v;
        }
        __syncwarp();

        // ---- compute: 8 columns x 2 matrices, this warp's 64 k's ----
        unsigned long long acc2[JC];
#pragma unroll
        for (int j = 0; j < JC; j++) acc2[j] = 0ull;

#pragma unroll 4
        for (int qq = 0; qq < 16; qq++) {
            int q = qbase + qq;
            float4 h4 = hs4[b * H4S + q];
            unsigned long long hx = dup2(h4.x);
            unsigned long long hy = dup2(h4.y);
            unsigned long long hz = dup2(h4.z);
            unsigned long long hw = dup2(h4.w);
#pragma unroll
            for (int j = 0; j < JC; j++) {
                ulonglong2 wA = wvd_u2[j * 512 + 2 * q];      // k=4q,4q+1
                ulonglong2 wB = wvd_u2[j * 512 + 2 * q + 1];  // k=4q+2,4q+3
                fma2(acc2[j], hx, wA.x);
                fma2(acc2[j], hy, wA.y);
                fma2(acc2[j], hz, wB.x);
                fma2(acc2[j], hw, wB.y);
            }
        }

        // ---- store split-K partials ----
#pragma unroll
        for (int j = 0; j < JC; j++)
            red2[(warp * JC + j) * RED_ROW + b] = acc2[j];
        __syncthreads();

        // ---- epilogue: fold 16 partials (packed, 2 chains), gates, write ----
        if (tid < 256) {
            unsigned long long sA = 0ull, sB = 0ull;
#pragma unroll
            for (int w = 0; w < 16; w += 2) {
                add2(sA, red2[((w + 0) * JC + ej) * RED_ROW + eb]);
                add2(sB, red2[((w + 1) * JC + ej) * RED_ROW + eb]);
            }
            add2(sA, sB);
            float2 p = unpk(sA);
            float sv = pre_xr + p.x;
            float sd = pre_xw + p.y;

            float hprev = hsf[eb * (H4S * 4) + jg];
            float delta = 1.f / (1.f + __expf(-sd));
            float hv    = tanhf(sv);
            float hn    = hprev + delta * (hv - hprev);  // (1-d)*hp + d*tanh(v)
            float g     = hn + pre_x + bg;
            float sil   = g / (1.f + __expf(-g));        // silu(g)
            out[eidx] = hn * sil;
            H[eidx + (size_t)B_ * D_] = hn;              // H[t+1]
        }

        if (t == T_ - 1) break;

        // ---- grid barrier: release-red counter + acquire poll ----
        __syncthreads();                   // all H[t+1] stores issued
        if (tid == 0) {
            arrive_release(&g_ctr);
            const unsigned want = (unsigned)(NCTA * (t + 1));
            while ((int)(ld_acquire(&g_ctr) - want) < 0) { }
        }
        __syncthreads();
    }
}

// ---------------------------------------------------------------------------
// Launch
// Inputs (metadata order): x, h0, R_h, R_x, R_delta, W_delta, b, b_delta, b_gate
// Output: outputs [T,B,D] followed by h [T+1,B,D], fp32.
// ---------------------------------------------------------------------------
extern "C" void kernel_launch(void* const* d_in, const int* in_sizes, int n_in,
                              void* d_out, int out_size)
{
    const float* x       = (const float*)d_in[0];
    const float* h0      = (const float*)d_in[1];
    const float* R_h     = (const float*)d_in[2];
    const float* R_x     = (const float*)d_in[3];
    const float* R_delta = (const float*)d_in[4];
    const float* W_delta = (const float*)d_in[5];
    const float* b       = (const float*)d_in[6];
    const float* b_delta = (const float*)d_in[7];
    const float* b_gate  = (const float*)d_in[8];

    float* out = (float*)d_out;
    float* H   = out + (size_t)T_ * B_ * D_;   // h region: [T+1, B, D]

    cudaFuncSetAttribute(scan_kernel,
                         cudaFuncAttributeMaxDynamicSharedMemorySize, SMEM_BYTES);
    cudaFuncSetAttribute(gemm_tc_kernel,
                         cudaFuncAttributeMaxDynamicSharedMemorySize,
                         GEMM_SMEM_BYTES);

    // bf16 hi/lo splits
    split_x_kernel<<<2048, 256>>>(x);
    {
        dim3 wg(512, 2);
        split_w_kernel<<<wg, 256>>>(R_x, W_delta);
    }

    // tensor-core precompute GEMMs (both weight matrices via z)
    dim3 ggrid(D_ / GBN, M_ / GBM, 2);
    gemm_tc_kernel<<<ggrid, 256, GEMM_SMEM_BYTES>>>(b, b_delta);

    copy_h0_kernel<<<(B_ * D_ + 255) / 256, 256>>>(h0, H);
    scan_kernel<<<NCTA, SB_, SMEM_BYTES>>>(x, R_h, R_delta, b_gate, out, H);
}